// round 15
// baseline (speedup 1.0000x reference)
#include <cuda_runtime.h>
#include <cuda_bf16.h>
#include <math.h>
#include <cstdint>

#define NB 32
#define NN 512
#define BC 8
#define NPART 16
#define KROWS 32                 // G rows per k-chunk
#define PSTRIDE (NB * NN * BC)   // 131072 floats per partial
#define CDEG 12                  // Chebyshev degree per segment (proven config)
#define NSEG 2
#define WQ 16                    // wpass h-split

// -------- static device scratch (allocation-free rule) --------
__device__ unsigned short g_Yh[(size_t)NB * NN * NN];   // bf16 bits
__device__ unsigned short g_Yl[(size_t)NB * NN * NN];   // bf16 bits
__device__ float g_G[(size_t)NB * NN * NN];             // H = Y Y^T
__device__ float g_PA[NPART * PSTRIDE];
__device__ float g_PB[NPART * PSTRIDE];
__device__ float g_V0[PSTRIDE];
__device__ float g_V1[PSTRIDE];
__device__ float g_V2[PSTRIDE];
__device__ float g_v[NB * NN];        // final unit u
__device__ float g_w[WQ * NB * NN];   // partial w = Y^T u
__device__ float g_ie[NB];            // per-batch 2/rho

// ---------------- luma + bf16 split ----------------
__global__ void lumasplit_kernel(const float* __restrict__ x,
                                 unsigned short* __restrict__ Yh,
                                 unsigned short* __restrict__ Yl) {
    int i = blockIdx.x * blockDim.x + threadIdx.x;   // float4 index
    const int per = NN * NN / 4;
    int b = i / per, p = i - b * per;
    const float4* X = (const float4*)x;
    float4 r  = X[(size_t)(b * 3 + 0) * per + p];
    float4 g  = X[(size_t)(b * 3 + 1) * per + p];
    float4 bl = X[(size_t)(b * 3 + 2) * per + p];
    float y0 = 0.299f * r.x + 0.587f * g.x + 0.114f * bl.x;
    float y1 = 0.299f * r.y + 0.587f * g.y + 0.114f * bl.y;
    float y2 = 0.299f * r.z + 0.587f * g.z + 0.114f * bl.z;
    float y3 = 0.299f * r.w + 0.587f * g.w + 0.114f * bl.w;
    __nv_bfloat16 h0 = __float2bfloat16_rn(y0);
    __nv_bfloat16 h1 = __float2bfloat16_rn(y1);
    __nv_bfloat16 h2 = __float2bfloat16_rn(y2);
    __nv_bfloat16 h3 = __float2bfloat16_rn(y3);
    __nv_bfloat16 l0 = __float2bfloat16_rn(y0 - __bfloat162float(h0));
    __nv_bfloat16 l1 = __float2bfloat16_rn(y1 - __bfloat162float(h1));
    __nv_bfloat16 l2 = __float2bfloat16_rn(y2 - __bfloat162float(h2));
    __nv_bfloat16 l3 = __float2bfloat16_rn(y3 - __bfloat162float(h3));
    ushort4 ph, pl;
    ph.x = __bfloat16_as_ushort(h0); ph.y = __bfloat16_as_ushort(h1);
    ph.z = __bfloat16_as_ushort(h2); ph.w = __bfloat16_as_ushort(h3);
    pl.x = __bfloat16_as_ushort(l0); pl.y = __bfloat16_as_ushort(l1);
    pl.z = __bfloat16_as_ushort(l2); pl.w = __bfloat16_as_ushort(l3);
    ((ushort4*)Yh)[i] = ph;
    ((ushort4*)Yl)[i] = pl;
}

// ======== warp-level HMMA gram: H ≈ Yh Yh^T + Yh Yl^T + Yl Yh^T (lo*lo dropped) ========
__device__ __forceinline__ void mma_bf16(float* d, const uint32_t* a, const uint32_t* b) {
    asm volatile(
        "mma.sync.aligned.m16n8k16.row.col.f32.bf16.bf16.f32 "
        "{%0,%1,%2,%3}, {%4,%5,%6,%7}, {%8,%9}, {%0,%1,%2,%3};"
        : "+f"(d[0]), "+f"(d[1]), "+f"(d[2]), "+f"(d[3])
        : "r"(a[0]), "r"(a[1]), "r"(a[2]), "r"(a[3]), "r"(b[0]), "r"(b[1]));
}

#define LDT 72                      // smem row stride in bf16 elems
#define TILE_B (128 * LDT * 2)      // 18432 bytes per operand tile
#define GRAM_SMEM (4 * TILE_B)      // 73728 bytes

__global__ void __launch_bounds__(256) mma_gram_kernel(
    const unsigned short* __restrict__ Yh, const unsigned short* __restrict__ Yl,
    float* __restrict__ G) {
    extern __shared__ char smem[];
    int tid = threadIdx.x;
    int wid = tid >> 5, lane = tid & 31;
    int m = blockIdx.x, b = blockIdx.y;
    int ti = 0, rem = m;
    while (rem >= 4 - ti) { rem -= 4 - ti; ti++; }
    int tj = ti + rem;                 // ti <= tj
    int diag = (ti == tj) ? 1 : 0;

    const unsigned short* Ah = Yh + (size_t)b * NN * NN + (size_t)ti * 128 * NN;
    const unsigned short* Al = Yl + (size_t)b * NN * NN + (size_t)ti * 128 * NN;
    const unsigned short* Bh = Yh + (size_t)b * NN * NN + (size_t)tj * 128 * NN;
    const unsigned short* Bl = Yl + (size_t)b * NN * NN + (size_t)tj * 128 * NN;

    unsigned short* smA[2];
    unsigned short* smB[2];
    smA[0] = (unsigned short*)smem;
    smA[1] = (unsigned short*)(smem + TILE_B);
    smB[0] = diag ? smA[0] : (unsigned short*)(smem + 2 * TILE_B);
    smB[1] = diag ? smA[1] : (unsigned short*)(smem + 3 * TILE_B);

    int wm = wid & 3;        // row block of 32
    int wn = wid >> 2;       // col block of 64
    int g = lane >> 2;       // 0..7
    int kp = (lane & 3) * 2; // 0,2,4,6

    float acc[2][8][4];
    #pragma unroll
    for (int mi = 0; mi < 2; mi++)
        #pragma unroll
        for (int ni = 0; ni < 8; ni++)
            #pragma unroll
            for (int q = 0; q < 4; q++) acc[mi][ni][q] = 0.f;

    for (int c = 0; c < 8; c++) {
        int k0 = c * 64;
        for (int t = tid; t < 1024; t += 256) {
            int row = t >> 3, f4 = t & 7;
            int soff = row * LDT + f4 * 8;
            size_t goff = (size_t)row * NN + k0 + f4 * 8;
            *(float4*)(smA[0] + soff) = *(const float4*)(Ah + goff);
            *(float4*)(smA[1] + soff) = *(const float4*)(Al + goff);
            if (!diag) {
                *(float4*)(smB[0] + soff) = *(const float4*)(Bh + goff);
                *(float4*)(smB[1] + soff) = *(const float4*)(Bl + goff);
            }
        }
        __syncthreads();
        #pragma unroll
        for (int ks = 0; ks < 4; ks++) {
            int kk = ks * 16 + kp;
            #pragma unroll
            for (int ca = 0; ca < 2; ca++) {
                const unsigned short* As = smA[ca];
                uint32_t afr[2][4];
                #pragma unroll
                for (int mi = 0; mi < 2; mi++) {
                    int r0 = wm * 32 + mi * 16 + g;
                    afr[mi][0] = *(const uint32_t*)(As + r0 * LDT + kk);
                    afr[mi][1] = *(const uint32_t*)(As + (r0 + 8) * LDT + kk);
                    afr[mi][2] = *(const uint32_t*)(As + r0 * LDT + kk + 8);
                    afr[mi][3] = *(const uint32_t*)(As + (r0 + 8) * LDT + kk + 8);
                }
                int cbmax = (ca == 1) ? 1 : 2;   // skip lo*lo pass
                for (int cb = 0; cb < cbmax; cb++) {
                    const unsigned short* Bs = smB[cb];
                    #pragma unroll
                    for (int ni = 0; ni < 8; ni++) {
                        int n0 = wn * 64 + ni * 8 + g;
                        uint32_t bfr[2];
                        bfr[0] = *(const uint32_t*)(Bs + n0 * LDT + kk);
                        bfr[1] = *(const uint32_t*)(Bs + n0 * LDT + kk + 8);
                        mma_bf16(acc[0][ni], afr[0], bfr);
                        mma_bf16(acc[1][ni], afr[1], bfr);
                    }
                }
            }
        }
        __syncthreads();
    }

    float* Gb = G + (size_t)b * NN * NN;
    int i0 = ti * 128, j0 = tj * 128;
    #pragma unroll
    for (int mi = 0; mi < 2; mi++) {
        #pragma unroll
        for (int ni = 0; ni < 8; ni++) {
            int r0 = i0 + wm * 32 + mi * 16 + g;
            int c0 = j0 + wn * 64 + ni * 8 + kp;
            float v0 = acc[mi][ni][0], v1 = acc[mi][ni][1];
            float v2 = acc[mi][ni][2], v3 = acc[mi][ni][3];
            *(float2*)&Gb[(size_t)r0 * NN + c0] = make_float2(v0, v1);
            *(float2*)&Gb[(size_t)(r0 + 8) * NN + c0] = make_float2(v2, v3);
            if (!diag) {
                Gb[(size_t)c0 * NN + r0] = v0;
                Gb[(size_t)(c0 + 1) * NN + r0] = v1;
                Gb[(size_t)c0 * NN + r0 + 8] = v2;
                Gb[(size_t)(c0 + 1) * NN + r0 + 8] = v3;
            }
        }
    }
}

// ---- trace -> inv_e = 2/rho, rho = 0.92 * 4 * tr / 512 ; also init V0 (fused) ----
__global__ void trace_kernel(const float* __restrict__ G, float* __restrict__ ie,
                             float* __restrict__ v0) {
    int b = blockIdx.x, r = threadIdx.x;   // 512 threads
    {
        int gbase = b * NN * BC + r * BC;
        #pragma unroll
        for (int c = 0; c < BC; c++) {
            int i = gbase + c;
            unsigned h = (unsigned)i * 2654435761u;
            h ^= h >> 16; h *= 2246822519u; h ^= h >> 13; h *= 3266489917u; h ^= h >> 16;
            v0[i] = (float)(h & 0xFFFF) * (1.0f / 65536.0f) - 0.5f;
        }
    }
    float d = G[(size_t)b * NN * NN + (size_t)r * NN + r];
    for (int off = 16; off; off >>= 1) d += __shfl_down_sync(0xffffffffu, d, off);
    __shared__ float red[16];
    int warp = r >> 5, lane = r & 31;
    if (lane == 0) red[warp] = d;
    __syncthreads();
    if (r == 0) {
        float tr = 0.f;
        for (int w = 0; w < 16; w++) tr += red[w];
        ie[b] = 278.26086956f / tr;   // 2*512/(0.92*4*tr)
    }
}

// ------ shared GEMV-block mainloop (8-deep batching, 32 k-rows, L1 bypass) ------
__device__ __forceinline__ void gemm_mainloop(const float* __restrict__ Gp,
                                              const float4* __restrict__ Vs4,
                                              float* acc) {
    #pragma unroll
    for (int j = 0; j < KROWS; j += 8) {
        float gg[8];
        #pragma unroll
        for (int u = 0; u < 8; u++) gg[u] = __ldcg(&Gp[(size_t)(j + u) * NN]);
        #pragma unroll
        for (int u = 0; u < 8; u++) {
            float g = gg[u];
            float4 v0 = Vs4[(j + u) * 2 + 0];
            float4 v1 = Vs4[(j + u) * 2 + 1];
            acc[0] = fmaf(g, v0.x, acc[0]);
            acc[1] = fmaf(g, v0.y, acc[1]);
            acc[2] = fmaf(g, v0.z, acc[2]);
            acc[3] = fmaf(g, v0.w, acc[3]);
            acc[4] = fmaf(g, v1.x, acc[4]);
            acc[5] = fmaf(g, v1.y, acc[5]);
            acc[6] = fmaf(g, v1.z, acc[6]);
            acc[7] = fmaf(g, v1.w, acc[7]);
        }
    }
}

// ---------------- P = G * V  (128 threads, grid (4, NB, 16)) ----------------
__global__ void __launch_bounds__(128) gemm0_kernel(
    const float* __restrict__ G, const float* __restrict__ V, float* __restrict__ P) {
    int b = blockIdx.y, z = blockIdx.z;
    int r = blockIdx.x * 128 + threadIdx.x;
    __shared__ float4 Vs4[64];     // 32 rows x 8 floats
    if (threadIdx.x < 64)
        Vs4[threadIdx.x] = ((const float4*)V)[b * 1024 + z * 64 + threadIdx.x];
    __syncthreads();
    const float* Gp = G + (size_t)b * NN * NN + (size_t)(z * KROWS) * NN + r;
    float acc[BC] = {};
    gemm_mainloop(Gp, Vs4, acc);
    float* o = P + (size_t)z * PSTRIDE + ((size_t)b * NN + r) * BC;
    *(float4*)&o[0] = make_float4(acc[0], acc[1], acc[2], acc[3]);
    *(float4*)&o[4] = make_float4(acc[4], acc[5], acc[6], acc[7]);
}

// ------ Chebyshev step (128 threads, grid (4, NB, 16)):
//        Vn = fa*ie*sum(Pin) + fb*Vc + fc*Vp ; Pout = G*Vn ------
__global__ void __launch_bounds__(128) gemmC_kernel(
    const float* __restrict__ G, const float* __restrict__ Pin,
    const float* __restrict__ Vc, const float* __restrict__ Vp,
    float* __restrict__ Pout, float* __restrict__ Vn,
    const float* __restrict__ ie, float fa, float fb, float fc) {
    int b = blockIdx.y, z = blockIdx.z;
    int r = blockIdx.x * 128 + threadIdx.x;
    __shared__ float4 Vs4[64];
    if (threadIdx.x < 64) {
        int base4 = b * 1024 + z * 64 + threadIdx.x;
        float4 a = make_float4(0.f, 0.f, 0.f, 0.f);
        #pragma unroll
        for (int p = 0; p < NPART; p++) {
            float4 c = ((const float4*)(Pin + (size_t)p * PSTRIDE))[base4];
            a.x += c.x; a.y += c.y; a.z += c.z; a.w += c.w;
        }
        float s = fa * ie[b];
        float4 vc = ((const float4*)Vc)[base4];
        float4 vp = ((const float4*)Vp)[base4];
        float4 vn;
        vn.x = s * a.x + fb * vc.x + fc * vp.x;
        vn.y = s * a.y + fb * vc.y + fc * vp.y;
        vn.z = s * a.z + fb * vc.z + fc * vp.z;
        vn.w = s * a.w + fb * vc.w + fc * vp.w;
        Vs4[threadIdx.x] = vn;
        if (blockIdx.x == 0) ((float4*)Vn)[base4] = vn;
    }
    __syncthreads();
    const float* Gp = G + (size_t)b * NN * NN + (size_t)(z * KROWS) * NN + r;
    float acc[BC] = {};
    gemm_mainloop(Gp, Vs4, acc);
    float* o = Pout + (size_t)z * PSTRIDE + ((size_t)b * NN + r) * BC;
    *(float4*)&o[0] = make_float4(acc[0], acc[1], acc[2], acc[3]);
    *(float4*)&o[4] = make_float4(acc[4], acc[5], acc[6], acc[7]);
}

// ------ fused segment tail: Vn_row = ie*sum(Pin) - Vc - 0.25*Vp, then CholQR, write Q ------
__global__ void qrC_kernel(const float* __restrict__ Pin,
                           const float* __restrict__ Vc, const float* __restrict__ Vp,
                           float* __restrict__ Vout, const float* __restrict__ ie) {
    int b = blockIdx.x, r = threadIdx.x;   // 512 threads, one row each
    int base4 = b * 1024 + r * 2;
    float w[BC];
    {
        float4 a0 = make_float4(0.f, 0.f, 0.f, 0.f);
        float4 a1 = make_float4(0.f, 0.f, 0.f, 0.f);
        #pragma unroll
        for (int p = 0; p < NPART; p++) {
            const float4* P4 = (const float4*)(Pin + (size_t)p * PSTRIDE);
            float4 c0 = P4[base4], c1 = P4[base4 + 1];
            a0.x += c0.x; a0.y += c0.y; a0.z += c0.z; a0.w += c0.w;
            a1.x += c1.x; a1.y += c1.y; a1.z += c1.z; a1.w += c1.w;
        }
        float s2 = ie[b];
        float4 vc0 = ((const float4*)Vc)[base4], vc1 = ((const float4*)Vc)[base4 + 1];
        float4 vp0 = ((const float4*)Vp)[base4], vp1 = ((const float4*)Vp)[base4 + 1];
        w[0] = s2 * a0.x - vc0.x - 0.25f * vp0.x;
        w[1] = s2 * a0.y - vc0.y - 0.25f * vp0.y;
        w[2] = s2 * a0.z - vc0.z - 0.25f * vp0.z;
        w[3] = s2 * a0.w - vc0.w - 0.25f * vp0.w;
        w[4] = s2 * a1.x - vc1.x - 0.25f * vp1.x;
        w[5] = s2 * a1.y - vc1.y - 0.25f * vp1.y;
        w[6] = s2 * a1.z - vc1.z - 0.25f * vp1.z;
        w[7] = s2 * a1.w - vc1.w - 0.25f * vp1.w;
    }

    float pr[36];
    {
        int e = 0;
        #pragma unroll
        for (int i = 0; i < BC; i++)
            #pragma unroll
            for (int j = i; j < BC; j++) pr[e++] = w[i] * w[j];
    }
    #pragma unroll
    for (int off2 = 16; off2; off2 >>= 1)
        #pragma unroll
        for (int e = 0; e < 36; e++)
            pr[e] += __shfl_down_sync(0xffffffffu, pr[e], off2);

    __shared__ float red[16][36];
    int warp = r >> 5, lane = r & 31;
    if (lane == 0)
        for (int e = 0; e < 36; e++) red[warp][e] = pr[e];
    __syncthreads();

    __shared__ float Rinv[BC][BC];
    if (r == 0) {
        float C[BC][BC];
        int e = 0;
        for (int i = 0; i < BC; i++)
            for (int j = i; j < BC; j++) {
                float s = 0.f;
                for (int wv = 0; wv < 16; wv++) s += red[wv][e];
                C[i][j] = s; C[j][i] = s; e++;
            }
        float tr = 0.f;
        for (int i = 0; i < BC; i++) tr += C[i][i];
        for (int i = 0; i < BC; i++) C[i][i] += tr * 1e-7f + 1e-30f;
        float R[BC][BC];
        for (int i = 0; i < BC; i++) {
            float d = C[i][i];
            for (int k = 0; k < i; k++) d -= R[k][i] * R[k][i];
            d = sqrtf(fmaxf(d, 1e-30f));
            R[i][i] = d;
            float inv = 1.f / d;
            for (int j = i + 1; j < BC; j++) {
                float s = C[i][j];
                for (int k = 0; k < i; k++) s -= R[k][i] * R[k][j];
                R[i][j] = s * inv;
            }
        }
        for (int i = 0; i < BC; i++)
            for (int j = 0; j < BC; j++) Rinv[i][j] = 0.f;
        for (int j = 0; j < BC; j++) {
            Rinv[j][j] = 1.f / R[j][j];
            for (int i = j - 1; i >= 0; i--) {
                float s = 0.f;
                for (int k = i + 1; k <= j; k++) s += R[i][k] * Rinv[k][j];
                Rinv[i][j] = -s / R[i][i];
            }
        }
    }
    __syncthreads();

    float v[BC];
    #pragma unroll
    for (int c = 0; c < BC; c++) {
        float s = 0.f;
        for (int i = 0; i <= c; i++) s += w[i] * Rinv[i][c];
        v[c] = s;
    }
    float* row = Vout + ((size_t)b * NN + r) * BC;
    *(float4*)&row[0] = make_float4(v[0], v[1], v[2], v[3]);
    *(float4*)&row[4] = make_float4(v[4], v[5], v[6], v[7]);
}

// ------- Rayleigh-Ritz: M = Q^T (G Q), top eigvec by repeated squaring, u = Q w -------
__global__ void ritz_kernel(const float* __restrict__ Q, const float* __restrict__ P,
                            float* __restrict__ vout) {
    int b = blockIdx.x, r = threadIdx.x;   // 512 threads
    size_t off = ((size_t)b * NN + r) * BC;
    float vr[BC], zr[BC] = {};
    #pragma unroll
    for (int c = 0; c < BC; c++) vr[c] = Q[off + c];
    #pragma unroll
    for (int p = 0; p < NPART; p++) {
        const float* cc = P + (size_t)p * PSTRIDE + off;
        #pragma unroll
        for (int c = 0; c < BC; c++) zr[c] += cc[c];
    }

    float pr[64];
    #pragma unroll
    for (int i = 0; i < BC; i++)
        #pragma unroll
        for (int j = 0; j < BC; j++) pr[i * 8 + j] = vr[i] * zr[j];
    #pragma unroll
    for (int off2 = 16; off2; off2 >>= 1)
        #pragma unroll
        for (int e = 0; e < 64; e++)
            pr[e] += __shfl_down_sync(0xffffffffu, pr[e], off2);

    __shared__ float red[16][64];
    int warp = r >> 5, lane = r & 31;
    if (lane == 0)
        for (int e = 0; e < 64; e++) red[warp][e] = pr[e];
    __syncthreads();

    __shared__ float M[64], Mn[64];
    __shared__ float sc[1];
    __shared__ int jstar[1];
    if (r < 64) {
        float s = 0.f;
        for (int wv = 0; wv < 16; wv++) s += red[wv][r];
        Mn[r] = s;
    }
    __syncthreads();
    if (r < 64) M[r] = 0.5f * (Mn[r] + Mn[(r & 7) * 8 + (r >> 3)]);
    __syncthreads();

    for (int it = 0; it < 28; it++) {
        if (r < 64) {
            int i = r >> 3, j = r & 7;
            float s = 0.f;
            #pragma unroll
            for (int k = 0; k < 8; k++) s = fmaf(M[i * 8 + k], M[k * 8 + j], s);
            Mn[r] = s;
        }
        __syncthreads();
        if (r == 0) {
            float mx = 0.f;
            for (int i = 0; i < 8; i++) mx = fmaxf(mx, Mn[i * 9]);
            sc[0] = 1.0f / fmaxf(mx, 1e-30f);
        }
        __syncthreads();
        if (r < 64) M[r] = Mn[r] * sc[0];
        __syncthreads();
    }
    if (r == 0) {
        float mx = -1.f; int js = 0;
        for (int i = 0; i < 8; i++) if (M[i * 9] > mx) { mx = M[i * 9]; js = i; }
        jstar[0] = js;
    }
    __syncthreads();
    int js = jstar[0];

    float vrow = 0.f;
    #pragma unroll
    for (int c = 0; c < BC; c++) vrow = fmaf(vr[c], M[c * 8 + js], vrow);

    float sq = vrow * vrow;
    #pragma unroll
    for (int off2 = 16; off2; off2 >>= 1) sq += __shfl_down_sync(0xffffffffu, sq, off2);
    __shared__ float nred[16];
    if (lane == 0) nred[warp] = sq;
    __syncthreads();
    __shared__ float ninv[1];
    if (r == 0) {
        float s = 0.f;
        for (int wv = 0; wv < 16; wv++) s += nred[wv];
        ninv[0] = rsqrtf(fmaxf(s, 1e-30f));
    }
    __syncthreads();
    vout[b * NN + r] = vrow * ninv[0];
}

// ----- w partial (16-way h-split, 4 accumulators): wpart[q][b][j] = sum Y[h][j] u[h] -----
__global__ void wpass_kernel(const unsigned short* __restrict__ Yh,
                             const unsigned short* __restrict__ Yl,
                             const float* __restrict__ u, float* __restrict__ wpart) {
    int q = blockIdx.x, b = blockIdx.y;   // q in 0..15, 32 rows each
    int j = threadIdx.x;                  // 512
    __shared__ float us[32];
    if (j < 32) us[j] = u[b * NN + q * 32 + j];
    __syncthreads();
    const unsigned short* Hh = Yh + (size_t)b * NN * NN + (size_t)q * 32 * NN;
    const unsigned short* Hl = Yl + (size_t)b * NN * NN + (size_t)q * 32 * NN;
    float a0 = 0.f, a1 = 0.f, a2 = 0.f, a3 = 0.f;
    #pragma unroll
    for (int h = 0; h < 32; h += 4) {
        float y0 = __bfloat162float(__ushort_as_bfloat16(Hh[(size_t)(h + 0) * NN + j]))
                 + __bfloat162float(__ushort_as_bfloat16(Hl[(size_t)(h + 0) * NN + j]));
        float y1 = __bfloat162float(__ushort_as_bfloat16(Hh[(size_t)(h + 1) * NN + j]))
                 + __bfloat162float(__ushort_as_bfloat16(Hl[(size_t)(h + 1) * NN + j]));
        float y2 = __bfloat162float(__ushort_as_bfloat16(Hh[(size_t)(h + 2) * NN + j]))
                 + __bfloat162float(__ushort_as_bfloat16(Hl[(size_t)(h + 2) * NN + j]));
        float y3 = __bfloat162float(__ushort_as_bfloat16(Hh[(size_t)(h + 3) * NN + j]))
                 + __bfloat162float(__ushort_as_bfloat16(Hl[(size_t)(h + 3) * NN + j]));
        a0 = fmaf(y0, us[h + 0], a0);
        a1 = fmaf(y1, us[h + 1], a1);
        a2 = fmaf(y2, us[h + 2], a2);
        a3 = fmaf(y3, us[h + 3], a3);
    }
    wpart[((size_t)q * NB + b) * NN + j] = (a0 + a1) + (a2 + a3);
}

// ---------------- outer: out[h][j] = u[h] * w[j] ----------------
__global__ void outer_kernel(const float* __restrict__ u, const float* __restrict__ wpart,
                             float* __restrict__ out) {
    int b = blockIdx.y;
    int rowbase = blockIdx.x * 16;
    int t = threadIdx.x;   // 256
    __shared__ float ws[NN];
    __shared__ float us[16];
    for (int j = t; j < NN; j += 256) {
        float s = 0.f;
        #pragma unroll
        for (int q = 0; q < WQ; q++) s += wpart[((size_t)q * NB + b) * NN + j];
        ws[j] = s;
    }
    if (t < 16) us[t] = u[b * NN + rowbase + t];
    __syncthreads();
    float* ob = out + (size_t)b * NN * NN;
    #pragma unroll
    for (int rr = 0; rr < 16; rr++) {
        float uu = us[rr];
        ob[(size_t)(rowbase + rr) * NN + t] = uu * ws[t];
        ob[(size_t)(rowbase + rr) * NN + t + 256] = uu * ws[t + 256];
    }
}

extern "C" void kernel_launch(void* const* d_in, const int* in_sizes, int n_in,
                              void* d_out, int out_size) {
    const float* x = (const float*)d_in[0];
    float* out = (float*)d_out;

    unsigned short *Yh, *Yl;
    float *G, *PA, *PB, *Vv, *Wp, *IE;
    float* Vb[3];
    cudaGetSymbolAddress((void**)&Yh, g_Yh);
    cudaGetSymbolAddress((void**)&Yl, g_Yl);
    cudaGetSymbolAddress((void**)&G, g_G);
    cudaGetSymbolAddress((void**)&PA, g_PA);
    cudaGetSymbolAddress((void**)&PB, g_PB);
    cudaGetSymbolAddress((void**)&Vb[0], g_V0);
    cudaGetSymbolAddress((void**)&Vb[1], g_V1);
    cudaGetSymbolAddress((void**)&Vb[2], g_V2);
    cudaGetSymbolAddress((void**)&Vv, g_v);
    cudaGetSymbolAddress((void**)&Wp, g_w);
    cudaGetSymbolAddress((void**)&IE, g_ie);

    cudaFuncSetAttribute(mma_gram_kernel, cudaFuncAttributeMaxDynamicSharedMemorySize, GRAM_SMEM);

    lumasplit_kernel<<<(NB * NN * NN / 4) / 256, 256>>>(x, Yh, Yl);
    mma_gram_kernel<<<dim3(10, NB), 256, GRAM_SMEM>>>(Yh, Yl, G);
    trace_kernel<<<NB, 512>>>(G, IE, Vb[0]);

    dim3 gg(4, NB, 16);
    int ic = 0;
    for (int seg = 0; seg < NSEG; seg++) {
        gemm0_kernel<<<gg, 128>>>(G, Vb[ic], PA);
        float *Pc = PA, *Pn = PB;
        int ip = ic;
        int inew = (ic + 1) % 3;
        gemmC_kernel<<<gg, 128>>>(G, Pc, Vb[ic], Vb[ic], Pn, Vb[inew], IE, 0.5f, -0.5f, 0.0f);
        ip = ic; ic = inew;
        { float* t = Pc; Pc = Pn; Pn = t; }
        for (int s = 2; s <= CDEG - 1; s++) {
            inew = 3 - ip - ic;
            gemmC_kernel<<<gg, 128>>>(G, Pc, Vb[ic], Vb[ip], Pn, Vb[inew], IE, 1.0f, -1.0f, -0.25f);
            ip = ic; ic = inew;
            { float* t = Pc; Pc = Pn; Pn = t; }
        }
        inew = 3 - ip - ic;
        qrC_kernel<<<NB, 512>>>(Pc, Vb[ic], Vb[ip], Vb[inew], IE);
        ic = inew;
    }
    gemm0_kernel<<<gg, 128>>>(G, Vb[ic], PA);
    ritz_kernel<<<NB, 512>>>(Vb[ic], PA, Vv);
    wpass_kernel<<<dim3(WQ, NB), 512>>>(Yh, Yl, Vv, Wp);
    outer_kernel<<<dim3(32, NB), 256>>>(Vv, Wp, out);
}

// round 16
// speedup vs baseline: 1.1291x; 1.1291x over previous
#include <cuda_runtime.h>
#include <cuda_bf16.h>
#include <math.h>
#include <cstdint>

#define NB 32
#define NN 512
#define BC 8
#define NPART 8
#define PSTRIDE (NB * NN * BC)   // 131072 floats per partial
#define CDEG 12                  // Chebyshev degree per segment (proven config)
#define NSEG 2
#define WQ 16                    // wpass h-split

// -------- static device scratch (allocation-free rule) --------
__device__ unsigned short g_Yh[(size_t)NB * NN * NN];   // bf16 bits
__device__ unsigned short g_Yl[(size_t)NB * NN * NN];   // bf16 bits
__device__ float g_G[(size_t)NB * NN * NN];             // H = Y Y^T
__device__ float g_PA[NPART * PSTRIDE];
__device__ float g_PB[NPART * PSTRIDE];
__device__ float g_V0[PSTRIDE];
__device__ float g_V1[PSTRIDE];
__device__ float g_V2[PSTRIDE];
__device__ float g_v[NB * NN];        // final unit u
__device__ float g_w[WQ * NB * NN];   // partial w = Y^T u
__device__ float g_ie[NB];            // per-batch 2/rho

// ---------------- luma + bf16 split ----------------
__global__ void lumasplit_kernel(const float* __restrict__ x,
                                 unsigned short* __restrict__ Yh,
                                 unsigned short* __restrict__ Yl) {
    int i = blockIdx.x * blockDim.x + threadIdx.x;   // float4 index
    const int per = NN * NN / 4;
    int b = i / per, p = i - b * per;
    const float4* X = (const float4*)x;
    float4 r  = X[(size_t)(b * 3 + 0) * per + p];
    float4 g  = X[(size_t)(b * 3 + 1) * per + p];
    float4 bl = X[(size_t)(b * 3 + 2) * per + p];
    float y0 = 0.299f * r.x + 0.587f * g.x + 0.114f * bl.x;
    float y1 = 0.299f * r.y + 0.587f * g.y + 0.114f * bl.y;
    float y2 = 0.299f * r.z + 0.587f * g.z + 0.114f * bl.z;
    float y3 = 0.299f * r.w + 0.587f * g.w + 0.114f * bl.w;
    __nv_bfloat16 h0 = __float2bfloat16_rn(y0);
    __nv_bfloat16 h1 = __float2bfloat16_rn(y1);
    __nv_bfloat16 h2 = __float2bfloat16_rn(y2);
    __nv_bfloat16 h3 = __float2bfloat16_rn(y3);
    __nv_bfloat16 l0 = __float2bfloat16_rn(y0 - __bfloat162float(h0));
    __nv_bfloat16 l1 = __float2bfloat16_rn(y1 - __bfloat162float(h1));
    __nv_bfloat16 l2 = __float2bfloat16_rn(y2 - __bfloat162float(h2));
    __nv_bfloat16 l3 = __float2bfloat16_rn(y3 - __bfloat162float(h3));
    ushort4 ph, pl;
    ph.x = __bfloat16_as_ushort(h0); ph.y = __bfloat16_as_ushort(h1);
    ph.z = __bfloat16_as_ushort(h2); ph.w = __bfloat16_as_ushort(h3);
    pl.x = __bfloat16_as_ushort(l0); pl.y = __bfloat16_as_ushort(l1);
    pl.z = __bfloat16_as_ushort(l2); pl.w = __bfloat16_as_ushort(l3);
    ((ushort4*)Yh)[i] = ph;
    ((ushort4*)Yl)[i] = pl;
}

// ======== warp-level HMMA gram: H ≈ Yh Yh^T + Yh Yl^T + Yl Yh^T (lo*lo dropped) ========
__device__ __forceinline__ void mma_bf16(float* d, const uint32_t* a, const uint32_t* b) {
    asm volatile(
        "mma.sync.aligned.m16n8k16.row.col.f32.bf16.bf16.f32 "
        "{%0,%1,%2,%3}, {%4,%5,%6,%7}, {%8,%9}, {%0,%1,%2,%3};"
        : "+f"(d[0]), "+f"(d[1]), "+f"(d[2]), "+f"(d[3])
        : "r"(a[0]), "r"(a[1]), "r"(a[2]), "r"(a[3]), "r"(b[0]), "r"(b[1]));
}

#define LDT 72                      // smem row stride in bf16 elems
#define TILE_B (128 * LDT * 2)      // 18432 bytes per operand tile
#define GRAM_SMEM (4 * TILE_B)      // 73728 bytes

__global__ void __launch_bounds__(256) mma_gram_kernel(
    const unsigned short* __restrict__ Yh, const unsigned short* __restrict__ Yl,
    float* __restrict__ G) {
    extern __shared__ char smem[];
    int tid = threadIdx.x;
    int wid = tid >> 5, lane = tid & 31;
    int m = blockIdx.x, b = blockIdx.y;
    int ti = 0, rem = m;
    while (rem >= 4 - ti) { rem -= 4 - ti; ti++; }
    int tj = ti + rem;                 // ti <= tj
    int diag = (ti == tj) ? 1 : 0;

    const unsigned short* Ah = Yh + (size_t)b * NN * NN + (size_t)ti * 128 * NN;
    const unsigned short* Al = Yl + (size_t)b * NN * NN + (size_t)ti * 128 * NN;
    const unsigned short* Bh = Yh + (size_t)b * NN * NN + (size_t)tj * 128 * NN;
    const unsigned short* Bl = Yl + (size_t)b * NN * NN + (size_t)tj * 128 * NN;

    unsigned short* smA[2];
    unsigned short* smB[2];
    smA[0] = (unsigned short*)smem;
    smA[1] = (unsigned short*)(smem + TILE_B);
    smB[0] = diag ? smA[0] : (unsigned short*)(smem + 2 * TILE_B);
    smB[1] = diag ? smA[1] : (unsigned short*)(smem + 3 * TILE_B);

    int wm = wid & 3;        // row block of 32
    int wn = wid >> 2;       // col block of 64
    int g = lane >> 2;       // 0..7
    int kp = (lane & 3) * 2; // 0,2,4,6

    float acc[2][8][4];
    #pragma unroll
    for (int mi = 0; mi < 2; mi++)
        #pragma unroll
        for (int ni = 0; ni < 8; ni++)
            #pragma unroll
            for (int q = 0; q < 4; q++) acc[mi][ni][q] = 0.f;

    for (int c = 0; c < 8; c++) {
        int k0 = c * 64;
        for (int t = tid; t < 1024; t += 256) {
            int row = t >> 3, f4 = t & 7;
            int soff = row * LDT + f4 * 8;
            size_t goff = (size_t)row * NN + k0 + f4 * 8;
            *(float4*)(smA[0] + soff) = *(const float4*)(Ah + goff);
            *(float4*)(smA[1] + soff) = *(const float4*)(Al + goff);
            if (!diag) {
                *(float4*)(smB[0] + soff) = *(const float4*)(Bh + goff);
                *(float4*)(smB[1] + soff) = *(const float4*)(Bl + goff);
            }
        }
        __syncthreads();
        #pragma unroll
        for (int ks = 0; ks < 4; ks++) {
            int kk = ks * 16 + kp;
            #pragma unroll
            for (int ca = 0; ca < 2; ca++) {
                const unsigned short* As = smA[ca];
                uint32_t afr[2][4];
                #pragma unroll
                for (int mi = 0; mi < 2; mi++) {
                    int r0 = wm * 32 + mi * 16 + g;
                    afr[mi][0] = *(const uint32_t*)(As + r0 * LDT + kk);
                    afr[mi][1] = *(const uint32_t*)(As + (r0 + 8) * LDT + kk);
                    afr[mi][2] = *(const uint32_t*)(As + r0 * LDT + kk + 8);
                    afr[mi][3] = *(const uint32_t*)(As + (r0 + 8) * LDT + kk + 8);
                }
                int cbmax = (ca == 1) ? 1 : 2;   // skip lo*lo pass
                for (int cb = 0; cb < cbmax; cb++) {
                    const unsigned short* Bs = smB[cb];
                    #pragma unroll
                    for (int ni = 0; ni < 8; ni++) {
                        int n0 = wn * 64 + ni * 8 + g;
                        uint32_t bfr[2];
                        bfr[0] = *(const uint32_t*)(Bs + n0 * LDT + kk);
                        bfr[1] = *(const uint32_t*)(Bs + n0 * LDT + kk + 8);
                        mma_bf16(acc[0][ni], afr[0], bfr);
                        mma_bf16(acc[1][ni], afr[1], bfr);
                    }
                }
            }
        }
        __syncthreads();
    }

    float* Gb = G + (size_t)b * NN * NN;
    int i0 = ti * 128, j0 = tj * 128;
    #pragma unroll
    for (int mi = 0; mi < 2; mi++) {
        #pragma unroll
        for (int ni = 0; ni < 8; ni++) {
            int r0 = i0 + wm * 32 + mi * 16 + g;
            int c0 = j0 + wn * 64 + ni * 8 + kp;
            float v0 = acc[mi][ni][0], v1 = acc[mi][ni][1];
            float v2 = acc[mi][ni][2], v3 = acc[mi][ni][3];
            *(float2*)&Gb[(size_t)r0 * NN + c0] = make_float2(v0, v1);
            *(float2*)&Gb[(size_t)(r0 + 8) * NN + c0] = make_float2(v2, v3);
            if (!diag) {
                Gb[(size_t)c0 * NN + r0] = v0;
                Gb[(size_t)(c0 + 1) * NN + r0] = v1;
                Gb[(size_t)c0 * NN + r0 + 8] = v2;
                Gb[(size_t)(c0 + 1) * NN + r0 + 8] = v3;
            }
        }
    }
}

// ---- trace -> inv_e = 2/rho, rho = 0.92 * 4 * tr / 512 ; also init V0 (fused) ----
__global__ void trace_kernel(const float* __restrict__ G, float* __restrict__ ie,
                             float* __restrict__ v0) {
    int b = blockIdx.x, r = threadIdx.x;   // 512 threads
    {
        int gbase = b * NN * BC + r * BC;
        #pragma unroll
        for (int c = 0; c < BC; c++) {
            int i = gbase + c;
            unsigned h = (unsigned)i * 2654435761u;
            h ^= h >> 16; h *= 2246822519u; h ^= h >> 13; h *= 3266489917u; h ^= h >> 16;
            v0[i] = (float)(h & 0xFFFF) * (1.0f / 65536.0f) - 0.5f;
        }
    }
    float d = G[(size_t)b * NN * NN + (size_t)r * NN + r];
    for (int off = 16; off; off >>= 1) d += __shfl_down_sync(0xffffffffu, d, off);
    __shared__ float red[16];
    int warp = r >> 5, lane = r & 31;
    if (lane == 0) red[warp] = d;
    __syncthreads();
    if (r == 0) {
        float tr = 0.f;
        for (int w = 0; w < 16; w++) tr += red[w];
        ie[b] = 278.26086956f / tr;   // 2*512/(0.92*4*tr)
    }
}

// ------ shared GEMV-block mainloop (proven R10/R14 form: 8-deep, 64 rows, L1 bypass) ------
__device__ __forceinline__ void gemm_mainloop(const float* __restrict__ Gp,
                                              const float4* __restrict__ Vs4,
                                              float* acc) {
    #pragma unroll
    for (int j = 0; j < 64; j += 8) {
        float gg[8];
        #pragma unroll
        for (int u = 0; u < 8; u++) gg[u] = __ldcg(&Gp[(size_t)(j + u) * NN]);
        #pragma unroll
        for (int u = 0; u < 8; u++) {
            float g = gg[u];
            float4 v0 = Vs4[(j + u) * 2 + 0];
            float4 v1 = Vs4[(j + u) * 2 + 1];
            acc[0] = fmaf(g, v0.x, acc[0]);
            acc[1] = fmaf(g, v0.y, acc[1]);
            acc[2] = fmaf(g, v0.z, acc[2]);
            acc[3] = fmaf(g, v0.w, acc[3]);
            acc[4] = fmaf(g, v1.x, acc[4]);
            acc[5] = fmaf(g, v1.y, acc[5]);
            acc[6] = fmaf(g, v1.z, acc[6]);
            acc[7] = fmaf(g, v1.w, acc[7]);
        }
    }
}

// ---------------- P = G * V  (128 threads, grid (4, NB, 8)) ----------------
__global__ void __launch_bounds__(128) gemm0_kernel(
    const float* __restrict__ G, const float* __restrict__ V, float* __restrict__ P) {
    int b = blockIdx.y, z = blockIdx.z;
    int r = blockIdx.x * 128 + threadIdx.x;
    __shared__ float4 Vs4[128];
    Vs4[threadIdx.x] = ((const float4*)V)[b * 1024 + z * 128 + threadIdx.x];
    __syncthreads();
    const float* Gp = G + (size_t)b * NN * NN + (size_t)(z * 64) * NN + r;
    float acc[BC] = {};
    gemm_mainloop(Gp, Vs4, acc);
    float* o = P + (size_t)z * PSTRIDE + ((size_t)b * NN + r) * BC;
    *(float4*)&o[0] = make_float4(acc[0], acc[1], acc[2], acc[3]);
    *(float4*)&o[4] = make_float4(acc[4], acc[5], acc[6], acc[7]);
}

// ------ Chebyshev step (128 threads, grid (4, NB, 8)):
//        Vn = fa*ie*sum(Pin) + fb*Vc + fc*Vp ; Pout = G*Vn ------
__global__ void __launch_bounds__(128) gemmC_kernel(
    const float* __restrict__ G, const float* __restrict__ Pin,
    const float* __restrict__ Vc, const float* __restrict__ Vp,
    float* __restrict__ Pout, float* __restrict__ Vn,
    const float* __restrict__ ie, float fa, float fb, float fc) {
    int b = blockIdx.y, z = blockIdx.z;
    int r = blockIdx.x * 128 + threadIdx.x;
    __shared__ float4 Vs4[128];
    int base4 = b * 1024 + z * 128 + threadIdx.x;
    {
        float4 a = make_float4(0.f, 0.f, 0.f, 0.f);
        #pragma unroll
        for (int p = 0; p < NPART; p++) {
            float4 c = ((const float4*)(Pin + (size_t)p * PSTRIDE))[base4];
            a.x += c.x; a.y += c.y; a.z += c.z; a.w += c.w;
        }
        float s = fa * ie[b];
        float4 vc = ((const float4*)Vc)[base4];
        float4 vp = ((const float4*)Vp)[base4];
        float4 vn;
        vn.x = s * a.x + fb * vc.x + fc * vp.x;
        vn.y = s * a.y + fb * vc.y + fc * vp.y;
        vn.z = s * a.z + fb * vc.z + fc * vp.z;
        vn.w = s * a.w + fb * vc.w + fc * vp.w;
        Vs4[threadIdx.x] = vn;
        if (blockIdx.x == 0) ((float4*)Vn)[base4] = vn;
    }
    __syncthreads();
    const float* Gp = G + (size_t)b * NN * NN + (size_t)(z * 64) * NN + r;
    float acc[BC] = {};
    gemm_mainloop(Gp, Vs4, acc);
    float* o = Pout + (size_t)z * PSTRIDE + ((size_t)b * NN + r) * BC;
    *(float4*)&o[0] = make_float4(acc[0], acc[1], acc[2], acc[3]);
    *(float4*)&o[4] = make_float4(acc[4], acc[5], acc[6], acc[7]);
}

// ------ fused segment tail: Vn_row = ie*sum(Pin) - Vc - 0.25*Vp, then CholQR, write Q ------
__global__ void qrC_kernel(const float* __restrict__ Pin,
                           const float* __restrict__ Vc, const float* __restrict__ Vp,
                           float* __restrict__ Vout, const float* __restrict__ ie) {
    int b = blockIdx.x, r = threadIdx.x;   // 512 threads, one row each
    int base4 = b * 1024 + r * 2;
    float w[BC];
    {
        float4 a0 = make_float4(0.f, 0.f, 0.f, 0.f);
        float4 a1 = make_float4(0.f, 0.f, 0.f, 0.f);
        #pragma unroll
        for (int p = 0; p < NPART; p++) {
            const float4* P4 = (const float4*)(Pin + (size_t)p * PSTRIDE);
            float4 c0 = P4[base4], c1 = P4[base4 + 1];
            a0.x += c0.x; a0.y += c0.y; a0.z += c0.z; a0.w += c0.w;
            a1.x += c1.x; a1.y += c1.y; a1.z += c1.z; a1.w += c1.w;
        }
        float s2 = ie[b];
        float4 vc0 = ((const float4*)Vc)[base4], vc1 = ((const float4*)Vc)[base4 + 1];
        float4 vp0 = ((const float4*)Vp)[base4], vp1 = ((const float4*)Vp)[base4 + 1];
        w[0] = s2 * a0.x - vc0.x - 0.25f * vp0.x;
        w[1] = s2 * a0.y - vc0.y - 0.25f * vp0.y;
        w[2] = s2 * a0.z - vc0.z - 0.25f * vp0.z;
        w[3] = s2 * a0.w - vc0.w - 0.25f * vp0.w;
        w[4] = s2 * a1.x - vc1.x - 0.25f * vp1.x;
        w[5] = s2 * a1.y - vc1.y - 0.25f * vp1.y;
        w[6] = s2 * a1.z - vc1.z - 0.25f * vp1.z;
        w[7] = s2 * a1.w - vc1.w - 0.25f * vp1.w;
    }

    float pr[36];
    {
        int e = 0;
        #pragma unroll
        for (int i = 0; i < BC; i++)
            #pragma unroll
            for (int j = i; j < BC; j++) pr[e++] = w[i] * w[j];
    }
    #pragma unroll
    for (int off2 = 16; off2; off2 >>= 1)
        #pragma unroll
        for (int e = 0; e < 36; e++)
            pr[e] += __shfl_down_sync(0xffffffffu, pr[e], off2);

    __shared__ float red[16][36];
    int warp = r >> 5, lane = r & 31;
    if (lane == 0)
        for (int e = 0; e < 36; e++) red[warp][e] = pr[e];
    __syncthreads();

    __shared__ float Rinv[BC][BC];
    if (r == 0) {
        float C[BC][BC];
        int e = 0;
        for (int i = 0; i < BC; i++)
            for (int j = i; j < BC; j++) {
                float s = 0.f;
                for (int wv = 0; wv < 16; wv++) s += red[wv][e];
                C[i][j] = s; C[j][i] = s; e++;
            }
        float tr = 0.f;
        for (int i = 0; i < BC; i++) tr += C[i][i];
        for (int i = 0; i < BC; i++) C[i][i] += tr * 1e-7f + 1e-30f;
        float R[BC][BC];
        for (int i = 0; i < BC; i++) {
            float d = C[i][i];
            for (int k = 0; k < i; k++) d -= R[k][i] * R[k][i];
            d = sqrtf(fmaxf(d, 1e-30f));
            R[i][i] = d;
            float inv = 1.f / d;
            for (int j = i + 1; j < BC; j++) {
                float s = C[i][j];
                for (int k = 0; k < i; k++) s -= R[k][i] * R[k][j];
                R[i][j] = s * inv;
            }
        }
        for (int i = 0; i < BC; i++)
            for (int j = 0; j < BC; j++) Rinv[i][j] = 0.f;
        for (int j = 0; j < BC; j++) {
            Rinv[j][j] = 1.f / R[j][j];
            for (int i = j - 1; i >= 0; i--) {
                float s = 0.f;
                for (int k = i + 1; k <= j; k++) s += R[i][k] * Rinv[k][j];
                Rinv[i][j] = -s / R[i][i];
            }
        }
    }
    __syncthreads();

    float v[BC];
    #pragma unroll
    for (int c = 0; c < BC; c++) {
        float s = 0.f;
        for (int i = 0; i <= c; i++) s += w[i] * Rinv[i][c];
        v[c] = s;
    }
    float* row = Vout + ((size_t)b * NN + r) * BC;
    *(float4*)&row[0] = make_float4(v[0], v[1], v[2], v[3]);
    *(float4*)&row[4] = make_float4(v[4], v[5], v[6], v[7]);
}

// ------- Rayleigh-Ritz: M = Q^T (G Q), top eigvec by repeated squaring, u = Q w -------
__global__ void ritz_kernel(const float* __restrict__ Q, const float* __restrict__ P,
                            float* __restrict__ vout) {
    int b = blockIdx.x, r = threadIdx.x;   // 512 threads
    size_t off = ((size_t)b * NN + r) * BC;
    float vr[BC], zr[BC] = {};
    #pragma unroll
    for (int c = 0; c < BC; c++) vr[c] = Q[off + c];
    #pragma unroll
    for (int p = 0; p < NPART; p++) {
        const float* cc = P + (size_t)p * PSTRIDE + off;
        #pragma unroll
        for (int c = 0; c < BC; c++) zr[c] += cc[c];
    }

    float pr[64];
    #pragma unroll
    for (int i = 0; i < BC; i++)
        #pragma unroll
        for (int j = 0; j < BC; j++) pr[i * 8 + j] = vr[i] * zr[j];
    #pragma unroll
    for (int off2 = 16; off2; off2 >>= 1)
        #pragma unroll
        for (int e = 0; e < 64; e++)
            pr[e] += __shfl_down_sync(0xffffffffu, pr[e], off2);

    __shared__ float red[16][64];
    int warp = r >> 5, lane = r & 31;
    if (lane == 0)
        for (int e = 0; e < 64; e++) red[warp][e] = pr[e];
    __syncthreads();

    __shared__ float M[64], Mn[64];
    __shared__ float sc[1];
    __shared__ int jstar[1];
    if (r < 64) {
        float s = 0.f;
        for (int wv = 0; wv < 16; wv++) s += red[wv][r];
        Mn[r] = s;
    }
    __syncthreads();
    if (r < 64) M[r] = 0.5f * (Mn[r] + Mn[(r & 7) * 8 + (r >> 3)]);
    __syncthreads();

    for (int it = 0; it < 28; it++) {
        if (r < 64) {
            int i = r >> 3, j = r & 7;
            float s = 0.f;
            #pragma unroll
            for (int k = 0; k < 8; k++) s = fmaf(M[i * 8 + k], M[k * 8 + j], s);
            Mn[r] = s;
        }
        __syncthreads();
        if (r == 0) {
            float mx = 0.f;
            for (int i = 0; i < 8; i++) mx = fmaxf(mx, Mn[i * 9]);
            sc[0] = 1.0f / fmaxf(mx, 1e-30f);
        }
        __syncthreads();
        if (r < 64) M[r] = Mn[r] * sc[0];
        __syncthreads();
    }
    if (r == 0) {
        float mx = -1.f; int js = 0;
        for (int i = 0; i < 8; i++) if (M[i * 9] > mx) { mx = M[i * 9]; js = i; }
        jstar[0] = js;
    }
    __syncthreads();
    int js = jstar[0];

    float vrow = 0.f;
    #pragma unroll
    for (int c = 0; c < BC; c++) vrow = fmaf(vr[c], M[c * 8 + js], vrow);

    float sq = vrow * vrow;
    #pragma unroll
    for (int off2 = 16; off2; off2 >>= 1) sq += __shfl_down_sync(0xffffffffu, sq, off2);
    __shared__ float nred[16];
    if (lane == 0) nred[warp] = sq;
    __syncthreads();
    __shared__ float ninv[1];
    if (r == 0) {
        float s = 0.f;
        for (int wv = 0; wv < 16; wv++) s += nred[wv];
        ninv[0] = rsqrtf(fmaxf(s, 1e-30f));
    }
    __syncthreads();
    vout[b * NN + r] = vrow * ninv[0];
}

// ----- w partial (16-way h-split, 4 accumulators): wpart[q][b][j] = sum Y[h][j] u[h] -----
__global__ void wpass_kernel(const unsigned short* __restrict__ Yh,
                             const unsigned short* __restrict__ Yl,
                             const float* __restrict__ u, float* __restrict__ wpart) {
    int q = blockIdx.x, b = blockIdx.y;   // q in 0..15, 32 rows each
    int j = threadIdx.x;                  // 512
    __shared__ float us[32];
    if (j < 32) us[j] = u[b * NN + q * 32 + j];
    __syncthreads();
    const unsigned short* Hh = Yh + (size_t)b * NN * NN + (size_t)q * 32 * NN;
    const unsigned short* Hl = Yl + (size_t)b * NN * NN + (size_t)q * 32 * NN;
    float a0 = 0.f, a1 = 0.f, a2 = 0.f, a3 = 0.f;
    #pragma unroll
    for (int h = 0; h < 32; h += 4) {
        float y0 = __bfloat162float(__ushort_as_bfloat16(Hh[(size_t)(h + 0) * NN + j]))
                 + __bfloat162float(__ushort_as_bfloat16(Hl[(size_t)(h + 0) * NN + j]));
        float y1 = __bfloat162float(__ushort_as_bfloat16(Hh[(size_t)(h + 1) * NN + j]))
                 + __bfloat162float(__ushort_as_bfloat16(Hl[(size_t)(h + 1) * NN + j]));
        float y2 = __bfloat162float(__ushort_as_bfloat16(Hh[(size_t)(h + 2) * NN + j]))
                 + __bfloat162float(__ushort_as_bfloat16(Hl[(size_t)(h + 2) * NN + j]));
        float y3 = __bfloat162float(__ushort_as_bfloat16(Hh[(size_t)(h + 3) * NN + j]))
                 + __bfloat162float(__ushort_as_bfloat16(Hl[(size_t)(h + 3) * NN + j]));
        a0 = fmaf(y0, us[h + 0], a0);
        a1 = fmaf(y1, us[h + 1], a1);
        a2 = fmaf(y2, us[h + 2], a2);
        a3 = fmaf(y3, us[h + 3], a3);
    }
    wpart[((size_t)q * NB + b) * NN + j] = (a0 + a1) + (a2 + a3);
}

// ---------------- outer: out[h][j] = u[h] * w[j]  (float4 stores) ----------------
__global__ void outer_kernel(const float* __restrict__ u, const float* __restrict__ wpart,
                             float* __restrict__ out) {
    int b = blockIdx.y;
    int rowbase = blockIdx.x * 16;
    int t = threadIdx.x;   // 256
    __shared__ float ws[NN];
    __shared__ float us[16];
    for (int j = t; j < NN; j += 256) {
        float s = 0.f;
        #pragma unroll
        for (int q = 0; q < WQ; q++) s += wpart[((size_t)q * NB + b) * NN + j];
        ws[j] = s;
    }
    if (t < 16) us[t] = u[b * NN + rowbase + t];
    __syncthreads();
    // 256 threads cover 2 rows x 128 float4 per iteration
    float4* ob4 = (float4*)(out + (size_t)b * NN * NN);
    const float4* ws4 = (const float4*)ws;
    int rsub = t >> 7;          // 0..1
    int f4 = t & 127;           // 0..127
    float4 wv = ws4[f4];
    #pragma unroll
    for (int rr = 0; rr < 8; rr++) {
        int row = rowbase + rr * 2 + rsub;
        float uu = us[rr * 2 + rsub];
        float4 o;
        o.x = uu * wv.x; o.y = uu * wv.y; o.z = uu * wv.z; o.w = uu * wv.w;
        ob4[(size_t)row * 128 + f4] = o;
    }
}

extern "C" void kernel_launch(void* const* d_in, const int* in_sizes, int n_in,
                              void* d_out, int out_size) {
    const float* x = (const float*)d_in[0];
    float* out = (float*)d_out;

    unsigned short *Yh, *Yl;
    float *G, *PA, *PB, *Vv, *Wp, *IE;
    float* Vb[3];
    cudaGetSymbolAddress((void**)&Yh, g_Yh);
    cudaGetSymbolAddress((void**)&Yl, g_Yl);
    cudaGetSymbolAddress((void**)&G, g_G);
    cudaGetSymbolAddress((void**)&PA, g_PA);
    cudaGetSymbolAddress((void**)&PB, g_PB);
    cudaGetSymbolAddress((void**)&Vb[0], g_V0);
    cudaGetSymbolAddress((void**)&Vb[1], g_V1);
    cudaGetSymbolAddress((void**)&Vb[2], g_V2);
    cudaGetSymbolAddress((void**)&Vv, g_v);
    cudaGetSymbolAddress((void**)&Wp, g_w);
    cudaGetSymbolAddress((void**)&IE, g_ie);

    cudaFuncSetAttribute(mma_gram_kernel, cudaFuncAttributeMaxDynamicSharedMemorySize, GRAM_SMEM);

    lumasplit_kernel<<<(NB * NN * NN / 4) / 256, 256>>>(x, Yh, Yl);
    mma_gram_kernel<<<dim3(10, NB), 256, GRAM_SMEM>>>(Yh, Yl, G);
    trace_kernel<<<NB, 512>>>(G, IE, Vb[0]);

    dim3 gg(4, NB, 8);
    int ic = 0;
    for (int seg = 0; seg < NSEG; seg++) {
        gemm0_kernel<<<gg, 128>>>(G, Vb[ic], PA);
        float *Pc = PA, *Pn = PB;
        int ip = ic;
        int inew = (ic + 1) % 3;
        gemmC_kernel<<<gg, 128>>>(G, Pc, Vb[ic], Vb[ic], Pn, Vb[inew], IE, 0.5f, -0.5f, 0.0f);
        ip = ic; ic = inew;
        { float* t = Pc; Pc = Pn; Pn = t; }
        for (int s = 2; s <= CDEG - 1; s++) {
            inew = 3 - ip - ic;
            gemmC_kernel<<<gg, 128>>>(G, Pc, Vb[ic], Vb[ip], Pn, Vb[inew], IE, 1.0f, -1.0f, -0.25f);
            ip = ic; ic = inew;
            { float* t = Pc; Pc = Pn; Pn = t; }
        }
        inew = 3 - ip - ic;
        qrC_kernel<<<NB, 512>>>(Pc, Vb[ic], Vb[ip], Vb[inew], IE);
        ic = inew;
    }
    gemm0_kernel<<<gg, 128>>>(G, Vb[ic], PA);
    ritz_kernel<<<NB, 512>>>(Vb[ic], PA, Vv);
    wpass_kernel<<<dim3(WQ, NB), 512>>>(Yh, Yl, Vv, Wp);
    outer_kernel<<<dim3(32, NB), 256>>>(Vv, Wp, out);
}

// round 17
// speedup vs baseline: 1.1642x; 1.0311x over previous
#include <cuda_runtime.h>
#include <cuda_bf16.h>
#include <math.h>
#include <cstdint>

#define NB 32
#define NN 512
#define BC 8
#define NPART 8
#define PSTRIDE (NB * NN * BC)   // 131072 floats per partial
#define NSEG 2
#define WQ 16                    // wpass h-split

// -------- static device scratch (allocation-free rule) --------
__device__ unsigned short g_Yh[(size_t)NB * NN * NN];   // bf16 bits
__device__ unsigned short g_Yl[(size_t)NB * NN * NN];   // bf16 bits
__device__ float g_G[(size_t)NB * NN * NN];             // H = Y Y^T
__device__ float g_PA[NPART * PSTRIDE];
__device__ float g_PB[NPART * PSTRIDE];
__device__ float g_V0[PSTRIDE];
__device__ float g_V1[PSTRIDE];
__device__ float g_V2[PSTRIDE];
__device__ float g_v[NB * NN];        // final unit u
__device__ float g_w[WQ * NB * NN];   // partial w = Y^T u
__device__ float g_ie[NB];            // per-batch 2/rho

// ---------------- luma + bf16 split ----------------
__global__ void lumasplit_kernel(const float* __restrict__ x,
                                 unsigned short* __restrict__ Yh,
                                 unsigned short* __restrict__ Yl) {
    int i = blockIdx.x * blockDim.x + threadIdx.x;   // float4 index
    const int per = NN * NN / 4;
    int b = i / per, p = i - b * per;
    const float4* X = (const float4*)x;
    float4 r  = X[(size_t)(b * 3 + 0) * per + p];
    float4 g  = X[(size_t)(b * 3 + 1) * per + p];
    float4 bl = X[(size_t)(b * 3 + 2) * per + p];
    float y0 = 0.299f * r.x + 0.587f * g.x + 0.114f * bl.x;
    float y1 = 0.299f * r.y + 0.587f * g.y + 0.114f * bl.y;
    float y2 = 0.299f * r.z + 0.587f * g.z + 0.114f * bl.z;
    float y3 = 0.299f * r.w + 0.587f * g.w + 0.114f * bl.w;
    __nv_bfloat16 h0 = __float2bfloat16_rn(y0);
    __nv_bfloat16 h1 = __float2bfloat16_rn(y1);
    __nv_bfloat16 h2 = __float2bfloat16_rn(y2);
    __nv_bfloat16 h3 = __float2bfloat16_rn(y3);
    __nv_bfloat16 l0 = __float2bfloat16_rn(y0 - __bfloat162float(h0));
    __nv_bfloat16 l1 = __float2bfloat16_rn(y1 - __bfloat162float(h1));
    __nv_bfloat16 l2 = __float2bfloat16_rn(y2 - __bfloat162float(h2));
    __nv_bfloat16 l3 = __float2bfloat16_rn(y3 - __bfloat162float(h3));
    ushort4 ph, pl;
    ph.x = __bfloat16_as_ushort(h0); ph.y = __bfloat16_as_ushort(h1);
    ph.z = __bfloat16_as_ushort(h2); ph.w = __bfloat16_as_ushort(h3);
    pl.x = __bfloat16_as_ushort(l0); pl.y = __bfloat16_as_ushort(l1);
    pl.z = __bfloat16_as_ushort(l2); pl.w = __bfloat16_as_ushort(l3);
    ((ushort4*)Yh)[i] = ph;
    ((ushort4*)Yl)[i] = pl;
}

// ======== warp-level HMMA gram: H ≈ Yh Yh^T + Yh Yl^T + Yl Yh^T (lo*lo dropped) ========
__device__ __forceinline__ void mma_bf16(float* d, const uint32_t* a, const uint32_t* b) {
    asm volatile(
        "mma.sync.aligned.m16n8k16.row.col.f32.bf16.bf16.f32 "
        "{%0,%1,%2,%3}, {%4,%5,%6,%7}, {%8,%9}, {%0,%1,%2,%3};"
        : "+f"(d[0]), "+f"(d[1]), "+f"(d[2]), "+f"(d[3])
        : "r"(a[0]), "r"(a[1]), "r"(a[2]), "r"(a[3]), "r"(b[0]), "r"(b[1]));
}

#define LDT 72                      // smem row stride in bf16 elems
#define TILE_B (128 * LDT * 2)      // 18432 bytes per operand tile
#define GRAM_SMEM (4 * TILE_B)      // 73728 bytes

__global__ void __launch_bounds__(256) mma_gram_kernel(
    const unsigned short* __restrict__ Yh, const unsigned short* __restrict__ Yl,
    float* __restrict__ G) {
    extern __shared__ char smem[];
    int tid = threadIdx.x;
    int wid = tid >> 5, lane = tid & 31;
    int m = blockIdx.x, b = blockIdx.y;
    int ti = 0, rem = m;
    while (rem >= 4 - ti) { rem -= 4 - ti; ti++; }
    int tj = ti + rem;                 // ti <= tj
    int diag = (ti == tj) ? 1 : 0;

    const unsigned short* Ah = Yh + (size_t)b * NN * NN + (size_t)ti * 128 * NN;
    const unsigned short* Al = Yl + (size_t)b * NN * NN + (size_t)ti * 128 * NN;
    const unsigned short* Bh = Yh + (size_t)b * NN * NN + (size_t)tj * 128 * NN;
    const unsigned short* Bl = Yl + (size_t)b * NN * NN + (size_t)tj * 128 * NN;

    unsigned short* smA[2];
    unsigned short* smB[2];
    smA[0] = (unsigned short*)smem;
    smA[1] = (unsigned short*)(smem + TILE_B);
    smB[0] = diag ? smA[0] : (unsigned short*)(smem + 2 * TILE_B);
    smB[1] = diag ? smA[1] : (unsigned short*)(smem + 3 * TILE_B);

    int wm = wid & 3;        // row block of 32
    int wn = wid >> 2;       // col block of 64
    int g = lane >> 2;       // 0..7
    int kp = (lane & 3) * 2; // 0,2,4,6

    float acc[2][8][4];
    #pragma unroll
    for (int mi = 0; mi < 2; mi++)
        #pragma unroll
        for (int ni = 0; ni < 8; ni++)
            #pragma unroll
            for (int q = 0; q < 4; q++) acc[mi][ni][q] = 0.f;

    for (int c = 0; c < 8; c++) {
        int k0 = c * 64;
        for (int t = tid; t < 1024; t += 256) {
            int row = t >> 3, f4 = t & 7;
            int soff = row * LDT + f4 * 8;
            size_t goff = (size_t)row * NN + k0 + f4 * 8;
            *(float4*)(smA[0] + soff) = *(const float4*)(Ah + goff);
            *(float4*)(smA[1] + soff) = *(const float4*)(Al + goff);
            if (!diag) {
                *(float4*)(smB[0] + soff) = *(const float4*)(Bh + goff);
                *(float4*)(smB[1] + soff) = *(const float4*)(Bl + goff);
            }
        }
        __syncthreads();
        #pragma unroll
        for (int ks = 0; ks < 4; ks++) {
            int kk = ks * 16 + kp;
            #pragma unroll
            for (int ca = 0; ca < 2; ca++) {
                const unsigned short* As = smA[ca];
                uint32_t afr[2][4];
                #pragma unroll
                for (int mi = 0; mi < 2; mi++) {
                    int r0 = wm * 32 + mi * 16 + g;
                    afr[mi][0] = *(const uint32_t*)(As + r0 * LDT + kk);
                    afr[mi][1] = *(const uint32_t*)(As + (r0 + 8) * LDT + kk);
                    afr[mi][2] = *(const uint32_t*)(As + r0 * LDT + kk + 8);
                    afr[mi][3] = *(const uint32_t*)(As + (r0 + 8) * LDT + kk + 8);
                }
                int cbmax = (ca == 1) ? 1 : 2;   // skip lo*lo pass
                for (int cb = 0; cb < cbmax; cb++) {
                    const unsigned short* Bs = smB[cb];
                    #pragma unroll
                    for (int ni = 0; ni < 8; ni++) {
                        int n0 = wn * 64 + ni * 8 + g;
                        uint32_t bfr[2];
                        bfr[0] = *(const uint32_t*)(Bs + n0 * LDT + kk);
                        bfr[1] = *(const uint32_t*)(Bs + n0 * LDT + kk + 8);
                        mma_bf16(acc[0][ni], afr[0], bfr);
                        mma_bf16(acc[1][ni], afr[1], bfr);
                    }
                }
            }
        }
        __syncthreads();
    }

    float* Gb = G + (size_t)b * NN * NN;
    int i0 = ti * 128, j0 = tj * 128;
    #pragma unroll
    for (int mi = 0; mi < 2; mi++) {
        #pragma unroll
        for (int ni = 0; ni < 8; ni++) {
            int r0 = i0 + wm * 32 + mi * 16 + g;
            int c0 = j0 + wn * 64 + ni * 8 + kp;
            float v0 = acc[mi][ni][0], v1 = acc[mi][ni][1];
            float v2 = acc[mi][ni][2], v3 = acc[mi][ni][3];
            *(float2*)&Gb[(size_t)r0 * NN + c0] = make_float2(v0, v1);
            *(float2*)&Gb[(size_t)(r0 + 8) * NN + c0] = make_float2(v2, v3);
            if (!diag) {
                Gb[(size_t)c0 * NN + r0] = v0;
                Gb[(size_t)(c0 + 1) * NN + r0] = v1;
                Gb[(size_t)c0 * NN + r0 + 8] = v2;
                Gb[(size_t)(c0 + 1) * NN + r0 + 8] = v3;
            }
        }
    }
}

// ---- trace -> inv_e = 2/rho, rho = 0.92 * 4 * tr / 512 ; also init V0 (fused) ----
__global__ void trace_kernel(const float* __restrict__ G, float* __restrict__ ie,
                             float* __restrict__ v0) {
    int b = blockIdx.x, r = threadIdx.x;   // 512 threads
    {
        int gbase = b * NN * BC + r * BC;
        #pragma unroll
        for (int c = 0; c < BC; c++) {
            int i = gbase + c;
            unsigned h = (unsigned)i * 2654435761u;
            h ^= h >> 16; h *= 2246822519u; h ^= h >> 13; h *= 3266489917u; h ^= h >> 16;
            v0[i] = (float)(h & 0xFFFF) * (1.0f / 65536.0f) - 0.5f;
        }
    }
    float d = G[(size_t)b * NN * NN + (size_t)r * NN + r];
    for (int off = 16; off; off >>= 1) d += __shfl_down_sync(0xffffffffu, d, off);
    __shared__ float red[16];
    int warp = r >> 5, lane = r & 31;
    if (lane == 0) red[warp] = d;
    __syncthreads();
    if (r == 0) {
        float tr = 0.f;
        for (int w = 0; w < 16; w++) tr += red[w];
        ie[b] = 278.26086956f / tr;   // 2*512/(0.92*4*tr)
    }
}

// ------ shared GEMV-block mainloop (proven form: 8-deep, 64 rows, L1 bypass) ------
__device__ __forceinline__ void gemm_mainloop(const float* __restrict__ Gp,
                                              const float4* __restrict__ Vs4,
                                              float* acc) {
    #pragma unroll
    for (int j = 0; j < 64; j += 8) {
        float gg[8];
        #pragma unroll
        for (int u = 0; u < 8; u++) gg[u] = __ldcg(&Gp[(size_t)(j + u) * NN]);
        #pragma unroll
        for (int u = 0; u < 8; u++) {
            float g = gg[u];
            float4 v0 = Vs4[(j + u) * 2 + 0];
            float4 v1 = Vs4[(j + u) * 2 + 1];
            acc[0] = fmaf(g, v0.x, acc[0]);
            acc[1] = fmaf(g, v0.y, acc[1]);
            acc[2] = fmaf(g, v0.z, acc[2]);
            acc[3] = fmaf(g, v0.w, acc[3]);
            acc[4] = fmaf(g, v1.x, acc[4]);
            acc[5] = fmaf(g, v1.y, acc[5]);
            acc[6] = fmaf(g, v1.z, acc[6]);
            acc[7] = fmaf(g, v1.w, acc[7]);
        }
    }
}

// ---------------- P = G * V  (128 threads, grid (4, NB, 8)) ----------------
__global__ void __launch_bounds__(128) gemm0_kernel(
    const float* __restrict__ G, const float* __restrict__ V, float* __restrict__ P) {
    int b = blockIdx.y, z = blockIdx.z;
    int r = blockIdx.x * 128 + threadIdx.x;
    __shared__ float4 Vs4[128];
    Vs4[threadIdx.x] = ((const float4*)V)[b * 1024 + z * 128 + threadIdx.x];
    __syncthreads();
    const float* Gp = G + (size_t)b * NN * NN + (size_t)(z * 64) * NN + r;
    float acc[BC] = {};
    gemm_mainloop(Gp, Vs4, acc);
    float* o = P + (size_t)z * PSTRIDE + ((size_t)b * NN + r) * BC;
    *(float4*)&o[0] = make_float4(acc[0], acc[1], acc[2], acc[3]);
    *(float4*)&o[4] = make_float4(acc[4], acc[5], acc[6], acc[7]);
}

// ------ Chebyshev step (128 threads, grid (4, NB, 8)):
//        Vn = fa*ie*sum(Pin) + fb*Vc + fc*Vp ; Pout = G*Vn ------
__global__ void __launch_bounds__(128) gemmC_kernel(
    const float* __restrict__ G, const float* __restrict__ Pin,
    const float* __restrict__ Vc, const float* __restrict__ Vp,
    float* __restrict__ Pout, float* __restrict__ Vn,
    const float* __restrict__ ie, float fa, float fb, float fc) {
    int b = blockIdx.y, z = blockIdx.z;
    int r = blockIdx.x * 128 + threadIdx.x;
    __shared__ float4 Vs4[128];
    int base4 = b * 1024 + z * 128 + threadIdx.x;
    {
        float4 a = make_float4(0.f, 0.f, 0.f, 0.f);
        #pragma unroll
        for (int p = 0; p < NPART; p++) {
            float4 c = ((const float4*)(Pin + (size_t)p * PSTRIDE))[base4];
            a.x += c.x; a.y += c.y; a.z += c.z; a.w += c.w;
        }
        float s = fa * ie[b];
        float4 vc = ((const float4*)Vc)[base4];
        float4 vp = ((const float4*)Vp)[base4];
        float4 vn;
        vn.x = s * a.x + fb * vc.x + fc * vp.x;
        vn.y = s * a.y + fb * vc.y + fc * vp.y;
        vn.z = s * a.z + fb * vc.z + fc * vp.z;
        vn.w = s * a.w + fb * vc.w + fc * vp.w;
        Vs4[threadIdx.x] = vn;
        if (blockIdx.x == 0) ((float4*)Vn)[base4] = vn;
    }
    __syncthreads();
    const float* Gp = G + (size_t)b * NN * NN + (size_t)(z * 64) * NN + r;
    float acc[BC] = {};
    gemm_mainloop(Gp, Vs4, acc);
    float* o = Pout + (size_t)z * PSTRIDE + ((size_t)b * NN + r) * BC;
    *(float4*)&o[0] = make_float4(acc[0], acc[1], acc[2], acc[3]);
    *(float4*)&o[4] = make_float4(acc[4], acc[5], acc[6], acc[7]);
}

// ------ fused segment tail: Vn_row = ie*sum(Pin) - Vc - 0.25*Vp, then CholQR, write Q ------
__global__ void qrC_kernel(const float* __restrict__ Pin,
                           const float* __restrict__ Vc, const float* __restrict__ Vp,
                           float* __restrict__ Vout, const float* __restrict__ ie) {
    int b = blockIdx.x, r = threadIdx.x;   // 512 threads, one row each
    int base4 = b * 1024 + r * 2;
    float w[BC];
    {
        float4 a0 = make_float4(0.f, 0.f, 0.f, 0.f);
        float4 a1 = make_float4(0.f, 0.f, 0.f, 0.f);
        #pragma unroll
        for (int p = 0; p < NPART; p++) {
            const float4* P4 = (const float4*)(Pin + (size_t)p * PSTRIDE);
            float4 c0 = P4[base4], c1 = P4[base4 + 1];
            a0.x += c0.x; a0.y += c0.y; a0.z += c0.z; a0.w += c0.w;
            a1.x += c1.x; a1.y += c1.y; a1.z += c1.z; a1.w += c1.w;
        }
        float s2 = ie[b];
        float4 vc0 = ((const float4*)Vc)[base4], vc1 = ((const float4*)Vc)[base4 + 1];
        float4 vp0 = ((const float4*)Vp)[base4], vp1 = ((const float4*)Vp)[base4 + 1];
        w[0] = s2 * a0.x - vc0.x - 0.25f * vp0.x;
        w[1] = s2 * a0.y - vc0.y - 0.25f * vp0.y;
        w[2] = s2 * a0.z - vc0.z - 0.25f * vp0.z;
        w[3] = s2 * a0.w - vc0.w - 0.25f * vp0.w;
        w[4] = s2 * a1.x - vc1.x - 0.25f * vp1.x;
        w[5] = s2 * a1.y - vc1.y - 0.25f * vp1.y;
        w[6] = s2 * a1.z - vc1.z - 0.25f * vp1.z;
        w[7] = s2 * a1.w - vc1.w - 0.25f * vp1.w;
    }

    float pr[36];
    {
        int e = 0;
        #pragma unroll
        for (int i = 0; i < BC; i++)
            #pragma unroll
            for (int j = i; j < BC; j++) pr[e++] = w[i] * w[j];
    }
    #pragma unroll
    for (int off2 = 16; off2; off2 >>= 1)
        #pragma unroll
        for (int e = 0; e < 36; e++)
            pr[e] += __shfl_down_sync(0xffffffffu, pr[e], off2);

    __shared__ float red[16][36];
    int warp = r >> 5, lane = r & 31;
    if (lane == 0)
        for (int e = 0; e < 36; e++) red[warp][e] = pr[e];
    __syncthreads();

    __shared__ float Rinv[BC][BC];
    if (r == 0) {
        float C[BC][BC];
        int e = 0;
        for (int i = 0; i < BC; i++)
            for (int j = i; j < BC; j++) {
                float s = 0.f;
                for (int wv = 0; wv < 16; wv++) s += red[wv][e];
                C[i][j] = s; C[j][i] = s; e++;
            }
        float tr = 0.f;
        for (int i = 0; i < BC; i++) tr += C[i][i];
        for (int i = 0; i < BC; i++) C[i][i] += tr * 1e-7f + 1e-30f;
        float R[BC][BC];
        for (int i = 0; i < BC; i++) {
            float d = C[i][i];
            for (int k = 0; k < i; k++) d -= R[k][i] * R[k][i];
            d = sqrtf(fmaxf(d, 1e-30f));
            R[i][i] = d;
            float inv = 1.f / d;
            for (int j = i + 1; j < BC; j++) {
                float s = C[i][j];
                for (int k = 0; k < i; k++) s -= R[k][i] * R[k][j];
                R[i][j] = s * inv;
            }
        }
        for (int i = 0; i < BC; i++)
            for (int j = 0; j < BC; j++) Rinv[i][j] = 0.f;
        for (int j = 0; j < BC; j++) {
            Rinv[j][j] = 1.f / R[j][j];
            for (int i = j - 1; i >= 0; i--) {
                float s = 0.f;
                for (int k = i + 1; k <= j; k++) s += R[i][k] * Rinv[k][j];
                Rinv[i][j] = -s / R[i][i];
            }
        }
    }
    __syncthreads();

    float v[BC];
    #pragma unroll
    for (int c = 0; c < BC; c++) {
        float s = 0.f;
        for (int i = 0; i <= c; i++) s += w[i] * Rinv[i][c];
        v[c] = s;
    }
    float* row = Vout + ((size_t)b * NN + r) * BC;
    *(float4*)&row[0] = make_float4(v[0], v[1], v[2], v[3]);
    *(float4*)&row[4] = make_float4(v[4], v[5], v[6], v[7]);
}

// ------- Rayleigh-Ritz: M = Q^T (G Q), top eigvec by repeated squaring, u = Q w -------
__global__ void ritz_kernel(const float* __restrict__ Q, const float* __restrict__ P,
                            float* __restrict__ vout) {
    int b = blockIdx.x, r = threadIdx.x;   // 512 threads
    size_t off = ((size_t)b * NN + r) * BC;
    float vr[BC], zr[BC] = {};
    #pragma unroll
    for (int c = 0; c < BC; c++) vr[c] = Q[off + c];
    #pragma unroll
    for (int p = 0; p < NPART; p++) {
        const float* cc = P + (size_t)p * PSTRIDE + off;
        #pragma unroll
        for (int c = 0; c < BC; c++) zr[c] += cc[c];
    }

    float pr[64];
    #pragma unroll
    for (int i = 0; i < BC; i++)
        #pragma unroll
        for (int j = 0; j < BC; j++) pr[i * 8 + j] = vr[i] * zr[j];
    #pragma unroll
    for (int off2 = 16; off2; off2 >>= 1)
        #pragma unroll
        for (int e = 0; e < 64; e++)
            pr[e] += __shfl_down_sync(0xffffffffu, pr[e], off2);

    __shared__ float red[16][64];
    int warp = r >> 5, lane = r & 31;
    if (lane == 0)
        for (int e = 0; e < 64; e++) red[warp][e] = pr[e];
    __syncthreads();

    __shared__ float M[64], Mn[64];
    __shared__ float sc[1];
    __shared__ int jstar[1];
    if (r < 64) {
        float s = 0.f;
        for (int wv = 0; wv < 16; wv++) s += red[wv][r];
        Mn[r] = s;
    }
    __syncthreads();
    if (r < 64) M[r] = 0.5f * (Mn[r] + Mn[(r & 7) * 8 + (r >> 3)]);
    __syncthreads();

    for (int it = 0; it < 14; it++) {
        if (r < 64) {
            int i = r >> 3, j = r & 7;
            float s = 0.f;
            #pragma unroll
            for (int k = 0; k < 8; k++) s = fmaf(M[i * 8 + k], M[k * 8 + j], s);
            Mn[r] = s;
        }
        __syncthreads();
        if (r == 0) {
            float mx = 0.f;
            for (int i = 0; i < 8; i++) mx = fmaxf(mx, Mn[i * 9]);
            sc[0] = 1.0f / fmaxf(mx, 1e-30f);
        }
        __syncthreads();
        if (r < 64) M[r] = Mn[r] * sc[0];
        __syncthreads();
    }
    if (r == 0) {
        float mx = -1.f; int js = 0;
        for (int i = 0; i < 8; i++) if (M[i * 9] > mx) { mx = M[i * 9]; js = i; }
        jstar[0] = js;
    }
    __syncthreads();
    int js = jstar[0];

    float vrow = 0.f;
    #pragma unroll
    for (int c = 0; c < BC; c++) vrow = fmaf(vr[c], M[c * 8 + js], vrow);

    float sq = vrow * vrow;
    #pragma unroll
    for (int off2 = 16; off2; off2 >>= 1) sq += __shfl_down_sync(0xffffffffu, sq, off2);
    __shared__ float nred[16];
    if (lane == 0) nred[warp] = sq;
    __syncthreads();
    __shared__ float ninv[1];
    if (r == 0) {
        float s = 0.f;
        for (int wv = 0; wv < 16; wv++) s += nred[wv];
        ninv[0] = rsqrtf(fmaxf(s, 1e-30f));
    }
    __syncthreads();
    vout[b * NN + r] = vrow * ninv[0];
}

// ----- w partial (16-way h-split, 4 accumulators): wpart[q][b][j] = sum Y[h][j] u[h] -----
__global__ void wpass_kernel(const unsigned short* __restrict__ Yh,
                             const unsigned short* __restrict__ Yl,
                             const float* __restrict__ u, float* __restrict__ wpart) {
    int q = blockIdx.x, b = blockIdx.y;   // q in 0..15, 32 rows each
    int j = threadIdx.x;                  // 512
    __shared__ float us[32];
    if (j < 32) us[j] = u[b * NN + q * 32 + j];
    __syncthreads();
    const unsigned short* Hh = Yh + (size_t)b * NN * NN + (size_t)q * 32 * NN;
    const unsigned short* Hl = Yl + (size_t)b * NN * NN + (size_t)q * 32 * NN;
    float a0 = 0.f, a1 = 0.f, a2 = 0.f, a3 = 0.f;
    #pragma unroll
    for (int h = 0; h < 32; h += 4) {
        float y0 = __bfloat162float(__ushort_as_bfloat16(Hh[(size_t)(h + 0) * NN + j]))
                 + __bfloat162float(__ushort_as_bfloat16(Hl[(size_t)(h + 0) * NN + j]));
        float y1 = __bfloat162float(__ushort_as_bfloat16(Hh[(size_t)(h + 1) * NN + j]))
                 + __bfloat162float(__ushort_as_bfloat16(Hl[(size_t)(h + 1) * NN + j]));
        float y2 = __bfloat162float(__ushort_as_bfloat16(Hh[(size_t)(h + 2) * NN + j]))
                 + __bfloat162float(__ushort_as_bfloat16(Hl[(size_t)(h + 2) * NN + j]));
        float y3 = __bfloat162float(__ushort_as_bfloat16(Hh[(size_t)(h + 3) * NN + j]))
                 + __bfloat162float(__ushort_as_bfloat16(Hl[(size_t)(h + 3) * NN + j]));
        a0 = fmaf(y0, us[h + 0], a0);
        a1 = fmaf(y1, us[h + 1], a1);
        a2 = fmaf(y2, us[h + 2], a2);
        a3 = fmaf(y3, us[h + 3], a3);
    }
    wpart[((size_t)q * NB + b) * NN + j] = (a0 + a1) + (a2 + a3);
}

// ---------------- outer: out[h][j] = u[h] * w[j]  (float4 stores) ----------------
__global__ void outer_kernel(const float* __restrict__ u, const float* __restrict__ wpart,
                             float* __restrict__ out) {
    int b = blockIdx.y;
    int rowbase = blockIdx.x * 16;
    int t = threadIdx.x;   // 256
    __shared__ float ws[NN];
    __shared__ float us[16];
    for (int j = t; j < NN; j += 256) {
        float s = 0.f;
        #pragma unroll
        for (int q = 0; q < WQ; q++) s += wpart[((size_t)q * NB + b) * NN + j];
        ws[j] = s;
    }
    if (t < 16) us[t] = u[b * NN + rowbase + t];
    __syncthreads();
    float4* ob4 = (float4*)(out + (size_t)b * NN * NN);
    const float4* ws4 = (const float4*)ws;
    int rsub = t >> 7;          // 0..1
    int f4 = t & 127;           // 0..127
    float4 wv = ws4[f4];
    #pragma unroll
    for (int rr = 0; rr < 8; rr++) {
        int row = rowbase + rr * 2 + rsub;
        float uu = us[rr * 2 + rsub];
        float4 o;
        o.x = uu * wv.x; o.y = uu * wv.y; o.z = uu * wv.z; o.w = uu * wv.w;
        ob4[(size_t)row * 128 + f4] = o;
    }
}

extern "C" void kernel_launch(void* const* d_in, const int* in_sizes, int n_in,
                              void* d_out, int out_size) {
    const float* x = (const float*)d_in[0];
    float* out = (float*)d_out;

    unsigned short *Yh, *Yl;
    float *G, *PA, *PB, *Vv, *Wp, *IE;
    float* Vb[3];
    cudaGetSymbolAddress((void**)&Yh, g_Yh);
    cudaGetSymbolAddress((void**)&Yl, g_Yl);
    cudaGetSymbolAddress((void**)&G, g_G);
    cudaGetSymbolAddress((void**)&PA, g_PA);
    cudaGetSymbolAddress((void**)&PB, g_PB);
    cudaGetSymbolAddress((void**)&Vb[0], g_V0);
    cudaGetSymbolAddress((void**)&Vb[1], g_V1);
    cudaGetSymbolAddress((void**)&Vb[2], g_V2);
    cudaGetSymbolAddress((void**)&Vv, g_v);
    cudaGetSymbolAddress((void**)&Wp, g_w);
    cudaGetSymbolAddress((void**)&IE, g_ie);

    cudaFuncSetAttribute(mma_gram_kernel, cudaFuncAttributeMaxDynamicSharedMemorySize, GRAM_SMEM);

    lumasplit_kernel<<<(NB * NN * NN / 4) / 256, 256>>>(x, Yh, Yl);
    mma_gram_kernel<<<dim3(10, NB), 256, GRAM_SMEM>>>(Yh, Yl, G);
    trace_kernel<<<NB, 512>>>(G, IE, Vb[0]);

    const int degs[NSEG] = {11, 12};   // asymmetric Chebyshev degrees
    dim3 gg(4, NB, 8);
    int ic = 0;
    for (int seg = 0; seg < NSEG; seg++) {
        gemm0_kernel<<<gg, 128>>>(G, Vb[ic], PA);
        float *Pc = PA, *Pn = PB;
        int ip = ic;
        int inew = (ic + 1) % 3;
        gemmC_kernel<<<gg, 128>>>(G, Pc, Vb[ic], Vb[ic], Pn, Vb[inew], IE, 0.5f, -0.5f, 0.0f);
        ip = ic; ic = inew;
        { float* t = Pc; Pc = Pn; Pn = t; }
        for (int s = 2; s <= degs[seg] - 1; s++) {
            inew = 3 - ip - ic;
            gemmC_kernel<<<gg, 128>>>(G, Pc, Vb[ic], Vb[ip], Pn, Vb[inew], IE, 1.0f, -1.0f, -0.25f);
            ip = ic; ic = inew;
            { float* t = Pc; Pc = Pn; Pn = t; }
        }
        inew = 3 - ip - ic;
        qrC_kernel<<<NB, 512>>>(Pc, Vb[ic], Vb[ip], Vb[inew], IE);
        ic = inew;
    }
    gemm0_kernel<<<gg, 128>>>(G, Vb[ic], PA);
    ritz_kernel<<<NB, 512>>>(Vb[ic], PA, Vv);
    wpass_kernel<<<dim3(WQ, NB), 512>>>(Yh, Yl, Vv, Wp);
    outer_kernel<<<dim3(32, NB), 256>>>(Vv, Wp, out);
}